// round 4
// baseline (speedup 1.0000x reference)
#include <cuda_runtime.h>
#include <cstdint>
#include <cstddef>
typedef unsigned long long ull;
#define C3 384

__device__ float g_xw[(size_t)1024 * 256 * C3];     // [t][b][384] gate pre-acts
__device__ float g_seq1[(size_t)1024 * 256 * 128];  // [t][b][128] layer-1 outputs

__device__ __forceinline__ ull ffma2(ull a, ull b, ull c) {
    ull d; asm("fma.rn.f32x2 %0,%1,%2,%3;" : "=l"(d) : "l"(a), "l"(b), "l"(c)); return d;
}
__device__ __forceinline__ ull pack2(float x, float y) {
    ull d; asm("mov.b64 %0,{%1,%2};" : "=l"(d) : "f"(x), "f"(y)); return d;
}
__device__ __forceinline__ float2 up2(ull v) {
    float x, y; asm("mov.b64 {%0,%1},%2;" : "=f"(x), "=f"(y) : "l"(v)); return make_float2(x, y);
}
__device__ __forceinline__ float sigm(float x) {
    return __fdividef(1.f, 1.f + __expf(-x));
}

// out[t*256+b][c] = sum_k in[row][k]*W[k][c] + bias[c]; rows: L1 -> r=b*T+t, else r=t*256+b
template<int K, bool L1>
__global__ void __launch_bounds__(384, 1) k_xw(const float* __restrict__ in,
                                               const float* __restrict__ W,
                                               const float* __restrict__ bias) {
    extern __shared__ __align__(16) char smraw[];
    ulonglong2* Wq = (ulonglong2*)smraw;              // [K/4][384] packed (w0w1,w2w3)
    float* xs = (float*)(smraw + (K / 4) * C3 * 16);  // [32][K]
    int c = threadIdx.x;
    // Stage packed weights once (persistent kernel)
    for (int i = c; i < (K / 4) * C3; i += 384) {
        int kq = i / C3, cc = i - kq * C3;
        const float* wp = W + (size_t)(4 * kq) * C3 + cc;
        Wq[i] = make_ulonglong2(pack2(wp[0], wp[C3]), pack2(wp[2 * C3], wp[3 * C3]));
    }
    float bc = bias[c];
    __syncthreads();

    for (int ch = blockIdx.x; ch < 8192; ch += gridDim.x) {
        int r0 = ch * 32;
        const float4* src = (const float4*)((L1 ? in : (const float*)g_seq1) + (size_t)r0 * K);
        __syncthreads();
        for (int i = c; i < 32 * K / 4; i += 384) ((float4*)xs)[i] = src[i];
        __syncthreads();
        ull acc[32];
#pragma unroll
        for (int r = 0; r < 32; r++) acc[r] = 0ull;
#pragma unroll 2
        for (int kq = 0; kq < K / 4; kq++) {
            ulonglong2 w = Wq[kq * C3 + c];
#pragma unroll
            for (int r = 0; r < 32; r++) {
                ulonglong2 x4 = *(const ulonglong2*)&xs[r * K + 4 * kq];
                acc[r] = ffma2(x4.x, w.x, acc[r]);
                acc[r] = ffma2(x4.y, w.y, acc[r]);
            }
        }
#pragma unroll
        for (int r = 0; r < 32; r++) {
            float2 v = up2(acc[r]);
            int rr = r0 + r;
            int orow = L1 ? ((rr & 1023) * 256 + (rr >> 10)) : rr;
            g_xw[(size_t)orow * C3 + c] = v.x + v.y + bc;
        }
    }
}

// Sequential GRU: 1 CTA = 2 batch rows; 384 threads = 384 gate columns.
// Recurrent weights register-resident (64 packed k-pairs); 4 accumulator chains.
template<bool WSEQ>
__global__ void __launch_bounds__(384, 1) k_gru(const float* __restrict__ Uw,
                                                const float* __restrict__ br,
                                                float* __restrict__ stateOut,
                                                float* __restrict__ xOut) {
    __shared__ __align__(16) float hs[2][128];
    __shared__ float r0s[C3], r1s[C3];
    int c = threadIdx.x, p = blockIdx.x;
    ull wp[64];
#pragma unroll
    for (int j = 0; j < 64; j++)
        wp[j] = pack2(Uw[(size_t)(2 * j) * C3 + c], Uw[(size_t)(2 * j + 1) * C3 + c]);
    float brc = br[c];
    if (c < 128) { hs[0][c] = 0.f; hs[1][c] = 0.f; }
    int u = c & 127, bl = (c >> 7) & 1;
    bool g = c < 256;
    int b = 2 * p + bl;
    const float* xq = g_xw + (size_t)b * C3 + u;
    float* sq = g_seq1 + (size_t)b * 128 + u;
    __syncthreads();
    for (int t = 0; t < 1024; t++) {
        float xz = 0.f, xr = 0.f, xh = 0.f;
        if (g) {  // prefetch this step's input projections (hidden under the dot)
            const float* q = xq + (size_t)t * (256 * C3);
            xz = q[0]; xr = q[128]; xh = q[256];
        }
        ull a0e = 0ull, a0o = 0ull, a1e = 0ull, a1o = 0ull;  // 4 chains
#pragma unroll 4
        for (int i = 0; i < 16; i++) {
            ulonglong2 h0a = *(const ulonglong2*)&hs[0][8 * i];
            ulonglong2 h1a = *(const ulonglong2*)&hs[1][8 * i];
            ulonglong2 h0b = *(const ulonglong2*)&hs[0][8 * i + 4];
            ulonglong2 h1b = *(const ulonglong2*)&hs[1][8 * i + 4];
            a0e = ffma2(h0a.x, wp[4 * i],     a0e);
            a0o = ffma2(h0a.y, wp[4 * i + 1], a0o);
            a1e = ffma2(h1a.x, wp[4 * i],     a1e);
            a1o = ffma2(h1a.y, wp[4 * i + 1], a1o);
            a0e = ffma2(h0b.x, wp[4 * i + 2], a0e);
            a0o = ffma2(h0b.y, wp[4 * i + 3], a0o);
            a1e = ffma2(h1b.x, wp[4 * i + 2], a1e);
            a1o = ffma2(h1b.y, wp[4 * i + 3], a1o);
        }
        {
            float2 ve = up2(a0e), vo = up2(a0o);
            r0s[c] = (ve.x + ve.y) + (vo.x + vo.y) + brc;
        }
        {
            float2 ve = up2(a1e), vo = up2(a1o);
            r1s[c] = (ve.x + ve.y) + (vo.x + vo.y) + brc;
        }
        __syncthreads();
        if (g) {
            const float* rs = bl ? r1s : r0s;
            float z  = sigm(xz + rs[u]);
            float r  = sigm(xr + rs[u + 128]);
            float hh = fmaxf(xh + r * rs[u + 256], 0.f);
            float hn = z * hs[bl][u] + (1.f - z) * hh;
            hs[bl][u] = hn;
            if (WSEQ) sq[(size_t)t * (256 * 128)] = hn;
            if (t == 1023) {
                stateOut[(size_t)b * 128 + u] = hn;
                if (xOut) xOut[(size_t)b * 128 + u] = hn;
            }
        }
        __syncthreads();
    }
}

extern "C" void kernel_launch(void* const* d_in, const int* in_sizes, int n_in,
                              void* d_out, int out_size) {
    const float* x  = (const float*)d_in[0];
    const float* W1 = (const float*)d_in[1];
    const float* U1 = (const float*)d_in[2];
    const float* b1 = (const float*)d_in[3];
    const float* W2 = (const float*)d_in[4];
    const float* U2 = (const float*)d_in[5];
    const float* b2 = (const float*)d_in[6];
    float* out = (float*)d_out;  // [x | state1 | state2], each 256*128

    int sm1 = (64 / 4) * C3 * 16 + 32 * 64 * 4;    // 106496
    int sm2 = (128 / 4) * C3 * 16 + 32 * 128 * 4;  // 212992
    cudaFuncSetAttribute(k_xw<64, true>,  cudaFuncAttributeMaxDynamicSharedMemorySize, sm1);
    cudaFuncSetAttribute(k_xw<128, false>, cudaFuncAttributeMaxDynamicSharedMemorySize, sm2);

    k_xw<64, true><<<148, 384, sm1>>>(x, W1, b1);
    k_gru<true><<<128, 384>>>(U1, b1 + C3, out + 32768, nullptr);
    k_xw<128, false><<<148, 384, sm2>>>(nullptr, W2, b2);
    k_gru<false><<<128, 384>>>(U2, b2 + C3, out + 65536, out);
}

// round 5
// speedup vs baseline: 1.5108x; 1.5108x over previous
#include <cuda_runtime.h>
#include <cstdint>
#include <cstddef>
typedef unsigned long long ull;
#define C3 384

__device__ float g_xw[(size_t)1024 * 256 * C3];     // [t][b][384] gate pre-acts
__device__ float g_seq1[(size_t)1024 * 256 * 128];  // [t][b][128] layer-1 outputs

__device__ __forceinline__ ull ffma2(ull a, ull b, ull c) {
    ull d; asm("fma.rn.f32x2 %0,%1,%2,%3;" : "=l"(d) : "l"(a), "l"(b), "l"(c)); return d;
}
__device__ __forceinline__ ull pack2(float x, float y) {
    ull d; asm("mov.b64 %0,{%1,%2};" : "=l"(d) : "f"(x), "f"(y)); return d;
}
__device__ __forceinline__ float2 up2(ull v) {
    float x, y; asm("mov.b64 {%0,%1},%2;" : "=f"(x), "=f"(y) : "l"(v)); return make_float2(x, y);
}
__device__ __forceinline__ float sigm(float x) {
    return __fdividef(1.f, 1.f + __expf(-x));
}
__device__ __forceinline__ void pfL2(const void* p) {
    asm volatile("prefetch.global.L2 [%0];" :: "l"(p));
}

// out[t*256+b][c] = sum_k in[row][k]*W[k][c] + bias[c]; rows: L1 -> r=b*T+t, else r=t*256+b
template<int K, bool L1>
__global__ void __launch_bounds__(384, 1) k_xw(const float* __restrict__ in,
                                               const float* __restrict__ W,
                                               const float* __restrict__ bias) {
    __shared__ __align__(16) float xs[32 * K];
    int c = threadIdx.x;
    float bc = bias[c];
    for (int ch = blockIdx.x; ch < 8192; ch += gridDim.x) {
        int r0 = ch * 32;
        const float4* src = (const float4*)((L1 ? in : (const float*)g_seq1) + (size_t)r0 * K);
        __syncthreads();
        for (int i = c; i < 32 * K / 4; i += 384) ((float4*)xs)[i] = src[i];
        __syncthreads();
        ull acc[32];
#pragma unroll
        for (int r = 0; r < 32; r++) acc[r] = 0ull;
        for (int kq = 0; kq < K / 4; kq++) {
            const float* wp = W + (size_t)(4 * kq) * C3 + c;
            ull wA = pack2(wp[0], wp[C3]);
            ull wB = pack2(wp[2 * C3], wp[3 * C3]);
#pragma unroll
            for (int r = 0; r < 32; r++) {
                ulonglong2 x4 = *(const ulonglong2*)&xs[r * K + 4 * kq];
                acc[r] = ffma2(x4.x, wA, acc[r]);
                acc[r] = ffma2(x4.y, wB, acc[r]);
            }
        }
#pragma unroll
        for (int r = 0; r < 32; r++) {
            float2 v = up2(acc[r]);
            int rr = r0 + r;
            int orow = L1 ? ((rr & 1023) * 256 + (rr >> 10)) : rr;
            g_xw[(size_t)orow * C3 + c] = v.x + v.y + bc;
        }
    }
}

// Sequential GRU: 1 CTA = 2 batch rows; 384 threads = 384 gate columns.
// Recurrent weights register-resident (64 packed k-pairs, 2 accumulator chains).
template<bool WSEQ>
__global__ void __launch_bounds__(384, 1) k_gru(const float* __restrict__ Uw,
                                                const float* __restrict__ br,
                                                float* __restrict__ stateOut,
                                                float* __restrict__ xOut) {
    __shared__ __align__(16) float hs[2][128];
    __shared__ float r0s[C3], r1s[C3];
    int c = threadIdx.x, p = blockIdx.x;
    ull wp[64];
#pragma unroll
    for (int j = 0; j < 64; j++)
        wp[j] = pack2(Uw[(size_t)(2 * j) * C3 + c], Uw[(size_t)(2 * j + 1) * C3 + c]);
    float brc = br[c];
    if (c < 128) { hs[0][c] = 0.f; hs[1][c] = 0.f; }
    int u = c & 127, bl = (c >> 7) & 1;
    bool g = c < 256;
    int b = 2 * p + bl;
    const float* xq = g_xw + (size_t)b * C3 + u;
    float* sq = g_seq1 + (size_t)b * 128 + u;
    bool pf = g && ((u & 31) == 0);   // one prefetcher per 128B line
    __syncthreads();
    for (int t = 0; t < 1024; t++) {
        float xz = 0.f, xr = 0.f, xh = 0.f;
        if (g) {  // this step's input projections: L2 hits (prefetched last step)
            const float* q = xq + (size_t)t * (256 * C3);
            xz = q[0]; xr = q[128]; xh = q[256];
        }
        if (pf && t < 1023) {  // warm L2 for step t+1 (no destination register)
            const float* q = xq + (size_t)(t + 1) * (256 * C3);
            pfL2(q); pfL2(q + 128); pfL2(q + 256);
        }
        ull a0 = 0ull, a1 = 0ull;
#pragma unroll
        for (int i = 0; i < 32; i++) {
            ulonglong2 h0 = *(const ulonglong2*)&hs[0][4 * i];
            ulonglong2 h1 = *(const ulonglong2*)&hs[1][4 * i];
            a0 = ffma2(h0.x, wp[2 * i], a0);
            a0 = ffma2(h0.y, wp[2 * i + 1], a0);
            a1 = ffma2(h1.x, wp[2 * i], a1);
            a1 = ffma2(h1.y, wp[2 * i + 1], a1);
        }
        { float2 v = up2(a0); r0s[c] = v.x + v.y + brc; }
        { float2 v = up2(a1); r1s[c] = v.x + v.y + brc; }
        __syncthreads();
        if (g) {
            const float* rs = bl ? r1s : r0s;
            float z  = sigm(xz + rs[u]);
            float r  = sigm(xr + rs[u + 128]);
            float hh = fmaxf(xh + r * rs[u + 256], 0.f);
            float hn = z * hs[bl][u] + (1.f - z) * hh;
            hs[bl][u] = hn;
            if (WSEQ) sq[(size_t)t * (256 * 128)] = hn;
            if (t == 1023) {
                stateOut[(size_t)b * 128 + u] = hn;
                if (xOut) xOut[(size_t)b * 128 + u] = hn;
            }
        }
        __syncthreads();
    }
}

extern "C" void kernel_launch(void* const* d_in, const int* in_sizes, int n_in,
                              void* d_out, int out_size) {
    const float* x  = (const float*)d_in[0];
    const float* W1 = (const float*)d_in[1];
    const float* U1 = (const float*)d_in[2];
    const float* b1 = (const float*)d_in[3];
    const float* W2 = (const float*)d_in[4];
    const float* U2 = (const float*)d_in[5];
    const float* b2 = (const float*)d_in[6];
    float* out = (float*)d_out;  // [x | state1 | state2], each 256*128
    k_xw<64, true><<<148, 384>>>(x, W1, b1);
    k_gru<true><<<128, 384>>>(U1, b1 + C3, out + 32768, nullptr);
    k_xw<128, false><<<148, 384>>>(nullptr, W2, b2);
    k_gru<false><<<128, 384>>>(U2, b2 + C3, out + 65536, out);
}

// round 6
// speedup vs baseline: 1.6549x; 1.0953x over previous
#include <cuda_runtime.h>
#include <cstdint>
#include <cstddef>
typedef unsigned long long ull;
#define C3 384

__device__ float g_xw[(size_t)1024 * 256 * C3];     // [t][b][384] gate pre-acts
__device__ float g_seq1[(size_t)1024 * 256 * 128];  // [t][b][128] layer-1 outputs

__device__ __forceinline__ ull ffma2(ull a, ull b, ull c) {
    ull d; asm("fma.rn.f32x2 %0,%1,%2,%3;" : "=l"(d) : "l"(a), "l"(b), "l"(c)); return d;
}
__device__ __forceinline__ ull pack2(float x, float y) {
    ull d; asm("mov.b64 %0,{%1,%2};" : "=l"(d) : "f"(x), "f"(y)); return d;
}
__device__ __forceinline__ float2 up2(ull v) {
    float x, y; asm("mov.b64 {%0,%1},%2;" : "=f"(x), "=f"(y) : "l"(v)); return make_float2(x, y);
}
__device__ __forceinline__ float sigm(float x) {
    return __fdividef(1.f, 1.f + __expf(-x));
}
__device__ __forceinline__ void pfL2(const void* p) {
    asm volatile("prefetch.global.L2 [%0];" :: "l"(p));
}

// ============================================================
// k_xw v2: out[t*256+b][c] = sum_k in[row][k]*W[k][c] + bias[c]
// 64-row chunks; thread = (colpair cp, rowgroup rg of 32 rows).
// W staged ONCE in smem, packed per (k-pair j, colpair): no in-loop LDG.
// ============================================================
template<int K, bool L1>
__global__ void __launch_bounds__(384, 1) k_xw(const float* __restrict__ in,
                                               const float* __restrict__ W,
                                               const float* __restrict__ bias) {
    extern __shared__ __align__(16) char smraw[];
    ulonglong2* Wp = (ulonglong2*)smraw;                    // [K/2][192]
    float* xs = (float*)(smraw + (size_t)(K / 2) * 192 * 16);  // [64][K]
    int tid = threadIdx.x;
    int cp = tid % 192, rg = tid / 192;
    int rbase = rg * 32;

    // Stage packed weights once: Wp[j*192+cp] = {(W[2j][2cp],W[2j+1][2cp]), (W[2j][2cp+1],W[2j+1][2cp+1])}
    for (int i = tid; i < (K / 2) * 192; i += 384) {
        int j = i / 192, c2 = i % 192;
        const float* w0 = W + (size_t)(2 * j) * C3 + 2 * c2;
        Wp[i] = make_ulonglong2(pack2(w0[0], w0[C3]), pack2(w0[1], w0[C3 + 1]));
    }
    float b0 = bias[2 * cp], b1 = bias[2 * cp + 1];
    __syncthreads();

    for (int ch = blockIdx.x; ch < 4096; ch += gridDim.x) {
        int r0 = ch * 64;
        const float4* src = (const float4*)((L1 ? in : (const float*)g_seq1) + (size_t)r0 * K);
        __syncthreads();
        for (int i = tid; i < 64 * K / 4; i += 384) ((float4*)xs)[i] = src[i];
        __syncthreads();

        ull acc0[32], acc1[32];
#pragma unroll
        for (int r = 0; r < 32; r++) { acc0[r] = 0ull; acc1[r] = 0ull; }

        for (int kq = 0; kq < K / 4; kq++) {
            ulonglong2 wA = Wp[(2 * kq) * 192 + cp];
            ulonglong2 wB = Wp[(2 * kq + 1) * 192 + cp];
            const float* xrow = xs + (size_t)rbase * K + 4 * kq;
#pragma unroll
            for (int r = 0; r < 32; r++) {
                ulonglong2 x4 = *(const ulonglong2*)(xrow + (size_t)r * K);
                acc0[r] = ffma2(x4.x, wA.x, acc0[r]);
                acc1[r] = ffma2(x4.x, wA.y, acc1[r]);
                acc0[r] = ffma2(x4.y, wB.x, acc0[r]);
                acc1[r] = ffma2(x4.y, wB.y, acc1[r]);
            }
        }

#pragma unroll
        for (int r = 0; r < 32; r++) {
            float2 v0 = up2(acc0[r]), v1 = up2(acc1[r]);
            int rr = r0 + rbase + r;
            int orow = L1 ? ((rr & 1023) * 256 + (rr >> 10)) : rr;
            float2 o = make_float2(v0.x + v0.y + b0, v1.x + v1.y + b1);
            *(float2*)&g_xw[(size_t)orow * C3 + 2 * cp] = o;
        }
    }
}

// ============================================================
// k_gru (unchanged from R5): 1 CTA = 2 batch rows; 384 threads = 384 cols.
// Recurrent weights register-resident (64 packed k-pairs, 2 chains).
// ============================================================
template<bool WSEQ>
__global__ void __launch_bounds__(384, 1) k_gru(const float* __restrict__ Uw,
                                                const float* __restrict__ br,
                                                float* __restrict__ stateOut,
                                                float* __restrict__ xOut) {
    __shared__ __align__(16) float hs[2][128];
    __shared__ float r0s[C3], r1s[C3];
    int c = threadIdx.x, p = blockIdx.x;
    ull wp[64];
#pragma unroll
    for (int j = 0; j < 64; j++)
        wp[j] = pack2(Uw[(size_t)(2 * j) * C3 + c], Uw[(size_t)(2 * j + 1) * C3 + c]);
    float brc = br[c];
    if (c < 128) { hs[0][c] = 0.f; hs[1][c] = 0.f; }
    int u = c & 127, bl = (c >> 7) & 1;
    bool g = c < 256;
    int b = 2 * p + bl;
    const float* xq = g_xw + (size_t)b * C3 + u;
    float* sq = g_seq1 + (size_t)b * 128 + u;
    bool pf = g && ((u & 31) == 0);
    __syncthreads();
    for (int t = 0; t < 1024; t++) {
        float xz = 0.f, xr = 0.f, xh = 0.f;
        if (g) {
            const float* q = xq + (size_t)t * (256 * C3);
            xz = q[0]; xr = q[128]; xh = q[256];
        }
        if (pf && t < 1023) {
            const float* q = xq + (size_t)(t + 1) * (256 * C3);
            pfL2(q); pfL2(q + 128); pfL2(q + 256);
        }
        ull a0 = 0ull, a1 = 0ull;
#pragma unroll
        for (int i = 0; i < 32; i++) {
            ulonglong2 h0 = *(const ulonglong2*)&hs[0][4 * i];
            ulonglong2 h1 = *(const ulonglong2*)&hs[1][4 * i];
            a0 = ffma2(h0.x, wp[2 * i], a0);
            a0 = ffma2(h0.y, wp[2 * i + 1], a0);
            a1 = ffma2(h1.x, wp[2 * i], a1);
            a1 = ffma2(h1.y, wp[2 * i + 1], a1);
        }
        { float2 v = up2(a0); r0s[c] = v.x + v.y + brc; }
        { float2 v = up2(a1); r1s[c] = v.x + v.y + brc; }
        __syncthreads();
        if (g) {
            const float* rs = bl ? r1s : r0s;
            float z  = sigm(xz + rs[u]);
            float r  = sigm(xr + rs[u + 128]);
            float hh = fmaxf(xh + r * rs[u + 256], 0.f);
            float hn = z * hs[bl][u] + (1.f - z) * hh;
            hs[bl][u] = hn;
            if (WSEQ) sq[(size_t)t * (256 * 128)] = hn;
            if (t == 1023) {
                stateOut[(size_t)b * 128 + u] = hn;
                if (xOut) xOut[(size_t)b * 128 + u] = hn;
            }
        }
        __syncthreads();
    }
}

extern "C" void kernel_launch(void* const* d_in, const int* in_sizes, int n_in,
                              void* d_out, int out_size) {
    const float* x  = (const float*)d_in[0];
    const float* W1 = (const float*)d_in[1];
    const float* U1 = (const float*)d_in[2];
    const float* b1 = (const float*)d_in[3];
    const float* W2 = (const float*)d_in[4];
    const float* U2 = (const float*)d_in[5];
    const float* b2 = (const float*)d_in[6];
    float* out = (float*)d_out;  // [x | state1 | state2], each 256*128

    int sm1 = (64 / 2) * 192 * 16 + 64 * 64 * 4;     // 98304 + 16384 = 114688
    int sm2 = (128 / 2) * 192 * 16 + 64 * 128 * 4;   // 196608 + 32768 = 229376
    cudaFuncSetAttribute(k_xw<64, true>,   cudaFuncAttributeMaxDynamicSharedMemorySize, sm1);
    cudaFuncSetAttribute(k_xw<128, false>, cudaFuncAttributeMaxDynamicSharedMemorySize, sm2);

    k_xw<64, true><<<148, 384, sm1>>>(x, W1, b1);
    k_gru<true><<<128, 384>>>(U1, b1 + C3, out + 32768, nullptr);
    k_xw<128, false><<<148, 384, sm2>>>(nullptr, W2, b2);
    k_gru<false><<<128, 384>>>(U2, b2 + C3, out + 65536, out);
}